// round 2
// baseline (speedup 1.0000x reference)
#include <cuda_runtime.h>
#include <cuda_bf16.h>
#include <cstdint>

// Problem constants (fixed shapes per reference setup_inputs)
#define Bn      8
#define Nn      8192
#define Cn      64
#define NP      2048
#define NS      32
#define CIN     67
#define H1n     64
#define H2n     128
#define RADIUS2 0.01f

#define QPB     4      // queries per block in MLP kernel

// Scratch (allocation-free rule: __device__ globals)
__device__ int   g_idx[Bn * NP * NS];              // 2 MB
__device__ float g_featT[(size_t)Bn * Nn * Cn];    // 16 MB, (B,N,C)

// ---------------------------------------------------------------------------
// Kernel 1: ball query, one warp per query. Ordered first-NS collection via
// ballot + prefix popc, early exit once NS found, pad with first index.
// ---------------------------------------------------------------------------
__global__ void bq_kernel(const float* __restrict__ xyz, int* __restrict__ out_idx)
{
    int warp = (blockIdx.x * blockDim.x + threadIdx.x) >> 5;
    int lane = threadIdx.x & 31;
    if (warp >= Bn * NP) return;
    int b = warp / NP;
    int s = warp - b * NP;

    const float* xb = xyz + (size_t)b * Nn * 3;
    float qx = __ldg(&xb[s * 3 + 0]);
    float qy = __ldg(&xb[s * 3 + 1]);
    float qz = __ldg(&xb[s * 3 + 2]);

    int* outp = out_idx + (size_t)warp * NS;
    int cnt = 0;
    int first_idx = 0;

    for (int base = 0; base < Nn; base += 32) {
        int i = base + lane;
        float dx = __ldg(&xb[i * 3 + 0]) - qx;
        float dy = __ldg(&xb[i * 3 + 1]) - qy;
        float dz = __ldg(&xb[i * 3 + 2]) - qz;
        float d2 = dx * dx + dy * dy + dz * dz;
        unsigned bits = __ballot_sync(0xffffffffu, d2 < RADIUS2);
        if (bits) {
            if (cnt == 0) first_idx = base + __ffs(bits) - 1;
            if ((bits >> lane) & 1u) {
                int pos = cnt + __popc(bits & ((1u << lane) - 1u));
                if (pos < NS) outp[pos] = i;
            }
            cnt += __popc(bits);
            if (cnt >= NS) break;
        }
    }
    if (cnt < NS) {
        int slot = cnt + lane;
        if (slot < NS) outp[slot] = first_idx;
    }
}

// ---------------------------------------------------------------------------
// Kernel 2: copy new_xyz = xyz[:, :NP, :] into out[0 .. B*NP*3)
// ---------------------------------------------------------------------------
__global__ void copy_newxyz_kernel(const float* __restrict__ xyz, float* __restrict__ out)
{
    int t = blockIdx.x * blockDim.x + threadIdx.x;
    if (t < Bn * NP * 3) {
        int b = t / (NP * 3);
        int r = t - b * (NP * 3);
        out[t] = xyz[(size_t)b * Nn * 3 + r];
    }
}

// ---------------------------------------------------------------------------
// Kernel 3: transpose features (B,C,N) -> (B,N,C) so gathers are contiguous.
// ---------------------------------------------------------------------------
__global__ void transpose_kernel(const float* __restrict__ f, float* __restrict__ ft)
{
    __shared__ float tile[32][33];
    int b  = blockIdx.z;
    int c0 = blockIdx.y * 32;
    int n0 = blockIdx.x * 32;
    int tx = threadIdx.x, ty = threadIdx.y;

    const float* fb = f + (size_t)b * Cn * Nn;
    tile[ty][tx] = fb[(size_t)(c0 + ty) * Nn + (n0 + tx)];
    __syncthreads();
    ft[(size_t)b * Nn * Cn + (size_t)(n0 + ty) * Cn + (c0 + tx)] = tile[tx][ty];
}

// ---------------------------------------------------------------------------
// Kernel 4: fused group + MLP(67->64->128) + max over samples.
// 128 threads = QPB queries x 32 samples. Weights + h1 staged in smem.
// ---------------------------------------------------------------------------
// smem layout (floats):
//   W1s  [64][68]   (rows padded to 68; cols 67.. zeroed)
//   W2sT [64][132]  (W2 transposed: [k][o], o padded to 132)
//   b1s  [64]
//   b2s  [128]
//   h1s  [QPB][64][32]
#define W1S_SZ   (64 * 68)
#define W2ST_SZ  (64 * 132)
#define H1S_SZ   (QPB * 64 * 32)
#define SMEM_FLOATS (W1S_SZ + W2ST_SZ + 64 + 128 + H1S_SZ)

__global__ __launch_bounds__(128, 2) void mlp_kernel(
    const float* __restrict__ xyz,
    const int*   __restrict__ idx,
    const float* __restrict__ W1,
    const float* __restrict__ b1,
    const float* __restrict__ W2,
    const float* __restrict__ b2,
    float* __restrict__ out)
{
    extern __shared__ float smem[];
    float* W1s  = smem;
    float* W2sT = W1s + W1S_SZ;
    float* b1s  = W2sT + W2ST_SZ;
    float* b2s  = b1s + 64;
    float* h1s  = b2s + 128;

    const int t = threadIdx.x;

    // Stage weights
    for (int i = t; i < W1S_SZ; i += 128) {
        int o = i / 68, k = i - o * 68;
        W1s[i] = (k < CIN) ? W1[o * CIN + k] : 0.0f;
    }
    for (int i = t; i < W2ST_SZ; i += 128) {
        int k = i / 132, o = i - k * 132;
        W2sT[i] = (o < H2n) ? W2[o * H1n + k] : 0.0f;
    }
    if (t < 64) b1s[t] = b1[t];
    b2s[t] = b2[t & 127];   // 128 threads -> all of b2
    __syncthreads();

    const int q    = t >> 5;          // query within block
    const int lane = t & 31;          // sample index n
    const int gq   = blockIdx.x * QPB + q;
    const int b    = gq / NP;
    const int s    = gq - b * NP;

    const int id = idx[(size_t)gq * NS + lane];
    const float* xb = xyz + (size_t)b * Nn * 3;

    float g[68];
    g[0] = __ldg(&xb[id * 3 + 0]) - __ldg(&xb[s * 3 + 0]);
    g[1] = __ldg(&xb[id * 3 + 1]) - __ldg(&xb[s * 3 + 1]);
    g[2] = __ldg(&xb[id * 3 + 2]) - __ldg(&xb[s * 3 + 2]);
    {
        const float4* fp = (const float4*)(g_featT + ((size_t)b * Nn + id) * Cn);
        #pragma unroll
        for (int k4 = 0; k4 < 16; k4++) {
            float4 v = __ldg(&fp[k4]);
            g[3 + 4 * k4 + 0] = v.x;
            g[3 + 4 * k4 + 1] = v.y;
            g[3 + 4 * k4 + 2] = v.z;
            g[3 + 4 * k4 + 3] = v.w;
        }
    }
    g[67] = 0.0f;

    // Phase A: h1[o] = relu(W1 . g + b1), store to smem [q][o][n]
    float* h1q = h1s + q * (64 * 32);
    #pragma unroll 2
    for (int o = 0; o < H1n; o++) {
        const float4* wr = (const float4*)(W1s + o * 68);
        float a0 = 0.f, a1 = 0.f, a2 = 0.f, a3 = 0.f;
        #pragma unroll
        for (int k4 = 0; k4 < 17; k4++) {
            float4 w = wr[k4];
            a0 += w.x * g[4 * k4 + 0];
            a1 += w.y * g[4 * k4 + 1];
            a2 += w.z * g[4 * k4 + 2];
            a3 += w.w * g[4 * k4 + 3];
        }
        float acc = b1s[o] + ((a0 + a1) + (a2 + a3));
        h1q[o * 32 + lane] = fmaxf(acc, 0.0f);
    }
    __syncthreads();

    // Phase B: for each query in block, GEMM h2 = W2 @ h1, then max over n.
    const int og    = t >> 5;        // which 32-channel slab of the 128 outputs
    const int obase = og * 32;
    const int bq0   = blockIdx.x * QPB;

    for (int q2 = 0; q2 < QPB; q2++) {
        float acc[32];
        #pragma unroll
        for (int oo = 0; oo < 32; oo++) acc[oo] = b2s[obase + oo];

        const float* hq = h1s + q2 * (64 * 32);
        #pragma unroll 4
        for (int k = 0; k < H1n; k++) {
            float hv = hq[k * 32 + lane];
            const float4* wr = (const float4*)(W2sT + k * 132 + obase);
            #pragma unroll
            for (int j = 0; j < 8; j++) {
                float4 w = wr[j];
                acc[4 * j + 0] += w.x * hv;
                acc[4 * j + 1] += w.y * hv;
                acc[4 * j + 2] += w.z * hv;
                acc[4 * j + 3] += w.w * hv;
            }
        }

        const int gq2 = bq0 + q2;
        const int bb  = gq2 / NP;
        const int ss  = gq2 - bb * NP;
        float* op = out + (Bn * NP * 3) + ((size_t)bb * H2n) * NP + ss;

        #pragma unroll
        for (int oo = 0; oo < 32; oo++) {
            float v = acc[oo];
            v = fmaxf(v, __shfl_xor_sync(0xffffffffu, v, 16));
            v = fmaxf(v, __shfl_xor_sync(0xffffffffu, v, 8));
            v = fmaxf(v, __shfl_xor_sync(0xffffffffu, v, 4));
            v = fmaxf(v, __shfl_xor_sync(0xffffffffu, v, 2));
            v = fmaxf(v, __shfl_xor_sync(0xffffffffu, v, 1));
            if (lane == oo) op[(size_t)(obase + oo) * NP] = fmaxf(v, 0.0f);
        }
    }
}

// ---------------------------------------------------------------------------
extern "C" void kernel_launch(void* const* d_in, const int* in_sizes, int n_in,
                              void* d_out, int out_size)
{
    const float* xyz      = (const float*)d_in[0];
    const float* features = (const float*)d_in[1];
    const float* W1       = (const float*)d_in[2];
    const float* b1       = (const float*)d_in[3];
    const float* W2       = (const float*)d_in[4];
    const float* b2       = (const float*)d_in[5];
    float* out = (float*)d_out;

    static bool attr_set = false;
    if (!attr_set) {
        cudaFuncSetAttribute(mlp_kernel, cudaFuncAttributeMaxDynamicSharedMemorySize,
                             SMEM_FLOATS * (int)sizeof(float));
        attr_set = true;
    }

    // Resolve scratch symbols on device side (kernels reference globals directly).
    int*   idxp;
    float* ftp;
    cudaGetSymbolAddress((void**)&idxp, g_idx);
    cudaGetSymbolAddress((void**)&ftp, g_featT);

    // 1) transpose features (B,C,N)->(B,N,C)
    {
        dim3 blk(32, 32, 1);
        dim3 grd(Nn / 32, Cn / 32, Bn);
        transpose_kernel<<<grd, blk>>>(features, ftp);
    }
    // 2) ball query (one warp per query)
    {
        int warps = Bn * NP;
        int threads = 256;
        int blocks = (warps * 32 + threads - 1) / threads;
        bq_kernel<<<blocks, threads>>>(xyz, idxp);
    }
    // 3) new_xyz copy
    {
        int tot = Bn * NP * 3;
        copy_newxyz_kernel<<<(tot + 255) / 256, 256>>>(xyz, out);
    }
    // 4) fused group + MLP + max
    {
        int blocks = (Bn * NP) / QPB;
        mlp_kernel<<<blocks, 128, SMEM_FLOATS * (int)sizeof(float)>>>(
            xyz, idxp, W1, b1, W2, b2, out);
    }
}

// round 4
// speedup vs baseline: 1.3525x; 1.3525x over previous
#include <cuda_runtime.h>
#include <cuda_bf16.h>
#include <cstdint>

// Problem constants (fixed shapes per reference setup_inputs)
#define Bn      8
#define Nn      8192
#define Cn      64
#define NP      2048
#define NS      32
#define CIN     67
#define H1n     64
#define H2n     128
#define RADIUS2 0.01f

// Scratch (allocation-free rule: __device__ globals)
__device__ int   g_idx[Bn * NP * NS];              // 2 MB
__device__ float g_featT[(size_t)Bn * Nn * Cn];    // 16 MB, (B,N,C)

// ---------------------------------------------------------------------------
// f32x2 packed-FMA helpers (Blackwell FFMA2 — 2x fp32 FMA per issue)
// ---------------------------------------------------------------------------
__device__ __forceinline__ unsigned long long ffma2(
    unsigned long long a, unsigned long long b, unsigned long long c)
{
    unsigned long long d;
    asm("fma.rn.f32x2 %0, %1, %2, %3;" : "=l"(d) : "l"(a), "l"(b), "l"(c));
    return d;
}
__device__ __forceinline__ unsigned long long pack2(float lo, float hi)
{
    unsigned long long r;
    asm("mov.b64 %0, {%1, %2};" : "=l"(r) : "f"(lo), "f"(hi));
    return r;
}
__device__ __forceinline__ void unpack2(unsigned long long v, float& lo, float& hi)
{
    asm("mov.b64 {%0, %1}, %2;" : "=f"(lo), "=f"(hi) : "l"(v));
}

// ---------------------------------------------------------------------------
// Kernel 1: ball query (one warp per query) + fused new_xyz copy.
// ---------------------------------------------------------------------------
__global__ void bq_kernel(const float* __restrict__ xyz, int* __restrict__ out_idx,
                          float* __restrict__ out)
{
    int warp = (blockIdx.x * blockDim.x + threadIdx.x) >> 5;
    int lane = threadIdx.x & 31;
    if (warp >= Bn * NP) return;
    int b = warp / NP;
    int s = warp - b * NP;

    const float* xb = xyz + (size_t)b * Nn * 3;
    float qx = __ldg(&xb[s * 3 + 0]);
    float qy = __ldg(&xb[s * 3 + 1]);
    float qz = __ldg(&xb[s * 3 + 2]);

    // fused new_xyz copy
    if (lane < 3) out[(size_t)warp * 3 + lane] = __ldg(&xb[s * 3 + lane]);

    int* outp = out_idx + (size_t)warp * NS;
    int cnt = 0;
    int first_idx = 0;

    for (int base = 0; base < Nn; base += 32) {
        int i = base + lane;
        float dx = __ldg(&xb[i * 3 + 0]) - qx;
        float dy = __ldg(&xb[i * 3 + 1]) - qy;
        float dz = __ldg(&xb[i * 3 + 2]) - qz;
        float d2 = dx * dx + dy * dy + dz * dz;
        unsigned bits = __ballot_sync(0xffffffffu, d2 < RADIUS2);
        if (bits) {
            if (cnt == 0) first_idx = base + __ffs(bits) - 1;
            if ((bits >> lane) & 1u) {
                int pos = cnt + __popc(bits & ((1u << lane) - 1u));
                if (pos < NS) outp[pos] = i;
            }
            cnt += __popc(bits);
            if (cnt >= NS) break;
        }
    }
    if (cnt < NS) {
        int slot = cnt + lane;
        if (slot < NS) outp[slot] = first_idx;
    }
}

// ---------------------------------------------------------------------------
// Kernel 2: transpose features (B,C,N) -> (B,N,C) so gathers are contiguous.
// ---------------------------------------------------------------------------
__global__ void transpose_kernel(const float* __restrict__ f, float* __restrict__ ft)
{
    __shared__ float tile[32][33];
    int b  = blockIdx.z;
    int c0 = blockIdx.y * 32;
    int n0 = blockIdx.x * 32;
    int tx = threadIdx.x, ty = threadIdx.y;

    const float* fb = f + (size_t)b * Cn * Nn;
    tile[ty][tx] = fb[(size_t)(c0 + ty) * Nn + (n0 + tx)];
    __syncthreads();
    ft[(size_t)b * Nn * Cn + (size_t)(n0 + ty) * Cn + (c0 + tx)] = tile[tx][ty];
}

// ---------------------------------------------------------------------------
// Kernel 3: fused group + MLP(67->64->128) + max, register-tiled FFMA2 GEMM.
//
// Block: 256 threads, 256 rows (8 queries x 32 samples). tid = ty*8 + tx:
//   tx in [0,8)  : output-channel slab
//   ty in [0,32) : row group of 8 (r0 = ty*8); warp w covers query w.
//
// smem (floats):
//   aT  [68][256]  : A tile transposed (k-major), k=67 zero-padded row
//                    -- ALIASED by h1T [64][260] after phase A
//   w1d [68][8 chunks x 20] : W1 duplicated pairs (w,w), per-tx interleave
//   w2d [64][8 chunks x 36] : W2 duplicated pairs, per-tx interleave
//   b1s [64], b2s [128]
// All 16-byte vector accesses verified 16B-aligned:
//   aT:  k*256*4 and r0*4 both x16B.  w1d: tx*20*4=80B? -> 80%16==0 ✓ (tx even mult)
//   w2d: tx*36*4=144B ✓.  h1T: stride 260*4=1040B=65x16 ✓, r0*4 x32B ✓.
// ---------------------------------------------------------------------------
#define AT_F    (68 * 256)        // 17408 floats (h1T 64*260=16640 fits inside)
#define W1D_F   (68 * 160)        // 10880
#define W2D_F   (64 * 288)        // 18432
#define OFF_W1  AT_F
#define OFF_W2  (AT_F + W1D_F)
#define OFF_B1  (AT_F + W1D_F + W2D_F)
#define OFF_B2  (OFF_B1 + 64)
#define SMEM_FLOATS (OFF_B2 + 128)
#define H1_STRIDE 260

typedef unsigned long long ull;

__global__ __launch_bounds__(256, 1) void mlp_kernel(
    const float* __restrict__ xyz,
    const int*   __restrict__ idx,
    const float* __restrict__ W1,
    const float* __restrict__ b1,
    const float* __restrict__ W2,
    const float* __restrict__ b2,
    float* __restrict__ out)
{
    extern __shared__ float sm[];
    float* aT  = sm;
    float* w1d = sm + OFF_W1;
    float* w2d = sm + OFF_W2;
    float* b1s = sm + OFF_B1;
    float* b2s = sm + OFF_B2;

    const int tid = threadIdx.x;
    const int tx  = tid & 7;
    const int r0  = (tid >> 3) * 8;   // this thread's first row

    // ---- stage weights (duplicated pairs, per-tx interleaved chunks) ----
    for (int i = tid; i < 68 * 64; i += 256) {
        int k = i >> 6, o = i & 63;
        float w = (k < CIN) ? __ldg(&W1[o * CIN + k]) : 0.0f;
        int base = k * 160 + (o >> 3) * 20 + (o & 7) * 2;
        w1d[base] = w; w1d[base + 1] = w;
    }
    for (int i = tid; i < 64 * 128; i += 256) {
        int k = i >> 7, o = i & 127;
        float w = __ldg(&W2[o * H1n + k]);
        int base = k * 288 + (o >> 4) * 36 + (o & 15) * 2;
        w2d[base] = w; w2d[base + 1] = w;
    }
    if (tid < 64)  b1s[tid] = b1[tid];
    if (tid < 128) b2s[tid] = b2[tid];

    // ---- stage A tile: one row per thread ----
    {
        const int q  = tid >> 5;
        const int n  = tid & 31;
        const int gq = blockIdx.x * 8 + q;
        const int b  = gq >> 11;            // NP = 2048
        const int s  = gq & (NP - 1);
        const int id = idx[(size_t)gq * NS + n];
        const float* xb = xyz + (size_t)b * Nn * 3;

        aT[0 * 256 + tid] = __ldg(&xb[id * 3 + 0]) - __ldg(&xb[s * 3 + 0]);
        aT[1 * 256 + tid] = __ldg(&xb[id * 3 + 1]) - __ldg(&xb[s * 3 + 1]);
        aT[2 * 256 + tid] = __ldg(&xb[id * 3 + 2]) - __ldg(&xb[s * 3 + 2]);
        const float4* fp = (const float4*)(g_featT + ((size_t)b * Nn + id) * Cn);
        #pragma unroll
        for (int k4 = 0; k4 < 16; k4++) {
            float4 v = __ldg(&fp[k4]);
            aT[(3 + 4 * k4 + 0) * 256 + tid] = v.x;
            aT[(3 + 4 * k4 + 1) * 256 + tid] = v.y;
            aT[(3 + 4 * k4 + 2) * 256 + tid] = v.z;
            aT[(3 + 4 * k4 + 3) * 256 + tid] = v.w;
        }
        aT[67 * 256 + tid] = 0.0f;
    }
    __syncthreads();

    // ---- Phase A: h1 = relu(W1 . a + b1); thread = 8 rows x 8 outs ----
    ull acc[4][8];
    #pragma unroll
    for (int op = 0; op < 8; op++) {
        float bv = b1s[tx * 8 + op];
        ull bp = pack2(bv, bv);
        #pragma unroll
        for (int rp = 0; rp < 4; rp++) acc[rp][op] = bp;
    }

    #pragma unroll 2
    for (int k = 0; k < 68; k++) {
        const ulonglong2* ap = (const ulonglong2*)&aT[k * 256 + r0];
        ulonglong2 av0 = ap[0], av1 = ap[1];
        ull a[4] = { av0.x, av0.y, av1.x, av1.y };   // row pairs (r0,r0+1)...

        const ulonglong2* wp = (const ulonglong2*)&w1d[k * 160 + tx * 20];
        ulonglong2 wv0 = wp[0], wv1 = wp[1], wv2 = wp[2], wv3 = wp[3];
        ull w[8] = { wv0.x, wv0.y, wv1.x, wv1.y, wv2.x, wv2.y, wv3.x, wv3.y };

        #pragma unroll
        for (int rp = 0; rp < 4; rp++)
            #pragma unroll
            for (int op = 0; op < 8; op++)
                acc[rp][op] = ffma2(a[rp], w[op], acc[rp][op]);
    }
    __syncthreads();   // all aT reads done before aliasing as h1T

    // store relu(h1) as [o][r] (row pairs stay packed -> 64-bit stores)
    float* h1T = sm;
    #pragma unroll
    for (int op = 0; op < 8; op++) {
        int o = tx * 8 + op;
        float* hrow = h1T + o * H1_STRIDE + r0;
        #pragma unroll
        for (int rp = 0; rp < 4; rp++) {
            float lo, hi;
            unpack2(acc[rp][op], lo, hi);
            ull p = pack2(fmaxf(lo, 0.0f), fmaxf(hi, 0.0f));
            *(ull*)&hrow[2 * rp] = p;
        }
    }
    __syncthreads();

    // ---- Phase B: h2 = W2 . h1 + b2; thread = 8 rows x 16 outs ----
    ull acc2[4][16];
    #pragma unroll
    for (int j = 0; j < 16; j++) {
        float bv = b2s[tx * 16 + j];
        ull bp = pack2(bv, bv);
        #pragma unroll
        for (int rp = 0; rp < 4; rp++) acc2[rp][j] = bp;
    }

    #pragma unroll 2
    for (int k = 0; k < 64; k++) {
        const ulonglong2* hp = (const ulonglong2*)&h1T[k * H1_STRIDE + r0];
        ulonglong2 hv0 = hp[0], hv1 = hp[1];
        ull a[4] = { hv0.x, hv0.y, hv1.x, hv1.y };

        const ulonglong2* wp = (const ulonglong2*)&w2d[k * 288 + tx * 36];
        ull w[16];
        #pragma unroll
        for (int jj = 0; jj < 8; jj++) {
            ulonglong2 wv = wp[jj];
            w[2 * jj]     = wv.x;
            w[2 * jj + 1] = wv.y;
        }

        #pragma unroll
        for (int rp = 0; rp < 4; rp++)
            #pragma unroll
            for (int j = 0; j < 16; j++)
                acc2[rp][j] = ffma2(a[rp], w[j], acc2[rp][j]);
    }

    // ---- max over 32 samples + relu + write ----
    {
        const int w   = tid >> 5;               // warp == query in block
        const int gq  = blockIdx.x * 8 + w;
        const int b   = gq >> 11;
        const int s   = gq & (NP - 1);
        float* op_base = out + (Bn * NP * 3) + (size_t)b * H2n * NP + s;

        #pragma unroll
        for (int j = 0; j < 16; j++) {
            float m = -3.4e38f;
            #pragma unroll
            for (int rp = 0; rp < 4; rp++) {
                float lo, hi;
                unpack2(acc2[rp][j], lo, hi);
                m = fmaxf(m, fmaxf(lo, hi));
            }
            m = fmaxf(m, __shfl_xor_sync(0xffffffffu, m, 8));
            m = fmaxf(m, __shfl_xor_sync(0xffffffffu, m, 16));
            if (((tid >> 3) & 3) == 0)
                op_base[(size_t)(tx * 16 + j) * NP] = fmaxf(m, 0.0f);
        }
    }
}

// ---------------------------------------------------------------------------
extern "C" void kernel_launch(void* const* d_in, const int* in_sizes, int n_in,
                              void* d_out, int out_size)
{
    const float* xyz      = (const float*)d_in[0];
    const float* features = (const float*)d_in[1];
    const float* W1       = (const float*)d_in[2];
    const float* b1       = (const float*)d_in[3];
    const float* W2       = (const float*)d_in[4];
    const float* b2       = (const float*)d_in[5];
    float* out = (float*)d_out;

    static bool attr_set = false;
    if (!attr_set) {
        cudaFuncSetAttribute(mlp_kernel, cudaFuncAttributeMaxDynamicSharedMemorySize,
                             SMEM_FLOATS * (int)sizeof(float));
        attr_set = true;
    }

    int*   idxp;
    float* ftp;
    cudaGetSymbolAddress((void**)&idxp, g_idx);
    cudaGetSymbolAddress((void**)&ftp, g_featT);

    // 1) transpose features (B,C,N)->(B,N,C)
    {
        dim3 blk(32, 32, 1);
        dim3 grd(Nn / 32, Cn / 32, Bn);
        transpose_kernel<<<grd, blk>>>(features, ftp);
    }
    // 2) ball query + new_xyz copy
    {
        int warps = Bn * NP;
        int threads = 256;
        int blocks = (warps * 32 + threads - 1) / threads;
        bq_kernel<<<blocks, threads>>>(xyz, idxp, out);
    }
    // 3) fused group + MLP + max  (8 queries / block)
    {
        int blocks = (Bn * NP) / 8;
        mlp_kernel<<<blocks, 256, SMEM_FLOATS * (int)sizeof(float)>>>(
            xyz, idxp, W1, b1, W2, b2, out);
    }
}

// round 5
// speedup vs baseline: 2.2308x; 1.6494x over previous
#include <cuda_runtime.h>
#include <cuda_bf16.h>
#include <cstdint>

// Problem constants (fixed shapes per reference setup_inputs)
#define Bn      8
#define Nn      8192
#define Cn      64
#define NP      2048
#define NS      32
#define CIN     67
#define H1n     64
#define H2n     128
#define RADIUS2 0.01f

// Scratch (allocation-free rule: __device__ globals)
__device__ int   g_idx[Bn * NP * NS];              // 2 MB
__device__ float g_featT[(size_t)Bn * Nn * Cn];    // 16 MB, (B,N,C)

// ---------------------------------------------------------------------------
// tf32 helpers
// ---------------------------------------------------------------------------
__device__ __forceinline__ unsigned f2tf32(float f)
{
    unsigned u;
    asm("cvt.rna.tf32.f32 %0, %1;" : "=r"(u) : "f"(f));
    return u;
}

__device__ __forceinline__ void mma_tf32(float c[4], const unsigned a[4], const unsigned b[2])
{
    asm volatile(
        "mma.sync.aligned.m16n8k8.row.col.f32.tf32.tf32.f32 "
        "{%0,%1,%2,%3}, {%4,%5,%6,%7}, {%8,%9}, {%0,%1,%2,%3};"
        : "+f"(c[0]), "+f"(c[1]), "+f"(c[2]), "+f"(c[3])
        : "r"(a[0]), "r"(a[1]), "r"(a[2]), "r"(a[3]), "r"(b[0]), "r"(b[1]));
}

// ---------------------------------------------------------------------------
// Kernel 1: ball query (one warp per query) + fused new_xyz copy.
// ---------------------------------------------------------------------------
__global__ void bq_kernel(const float* __restrict__ xyz, int* __restrict__ out_idx,
                          float* __restrict__ out)
{
    int warp = (blockIdx.x * blockDim.x + threadIdx.x) >> 5;
    int lane = threadIdx.x & 31;
    if (warp >= Bn * NP) return;
    int b = warp / NP;
    int s = warp - b * NP;

    const float* xb = xyz + (size_t)b * Nn * 3;
    float qx = __ldg(&xb[s * 3 + 0]);
    float qy = __ldg(&xb[s * 3 + 1]);
    float qz = __ldg(&xb[s * 3 + 2]);

    if (lane < 3) out[(size_t)warp * 3 + lane] = __ldg(&xb[s * 3 + lane]);

    int* outp = out_idx + (size_t)warp * NS;
    int cnt = 0;
    int first_idx = 0;

    for (int base = 0; base < Nn; base += 32) {
        int i = base + lane;
        float dx = __ldg(&xb[i * 3 + 0]) - qx;
        float dy = __ldg(&xb[i * 3 + 1]) - qy;
        float dz = __ldg(&xb[i * 3 + 2]) - qz;
        float d2 = dx * dx + dy * dy + dz * dz;
        unsigned bits = __ballot_sync(0xffffffffu, d2 < RADIUS2);
        if (bits) {
            if (cnt == 0) first_idx = base + __ffs(bits) - 1;
            if ((bits >> lane) & 1u) {
                int pos = cnt + __popc(bits & ((1u << lane) - 1u));
                if (pos < NS) outp[pos] = i;
            }
            cnt += __popc(bits);
            if (cnt >= NS) break;
        }
    }
    if (cnt < NS) {
        int slot = cnt + lane;
        if (slot < NS) outp[slot] = first_idx;
    }
}

// ---------------------------------------------------------------------------
// Kernel 2: transpose features (B,C,N) -> (B,N,C) so gathers are contiguous.
// ---------------------------------------------------------------------------
__global__ void transpose_kernel(const float* __restrict__ f, float* __restrict__ ft)
{
    __shared__ float tile[32][33];
    int b  = blockIdx.z;
    int c0 = blockIdx.y * 32;
    int n0 = blockIdx.x * 32;
    int tx = threadIdx.x, ty = threadIdx.y;

    const float* fb = f + (size_t)b * Cn * Nn;
    tile[ty][tx] = fb[(size_t)(c0 + ty) * Nn + (n0 + tx)];
    __syncthreads();
    ft[(size_t)b * Nn * Cn + (size_t)(n0 + ty) * Cn + (c0 + tx)] = tile[tx][ty];
}

// ---------------------------------------------------------------------------
// Kernel 3: fused group + MLP(67->64->128) + max, tf32 mma.sync tensor GEMMs.
//
// Block: 256 threads = 8 warps; warp w owns query w (32 sample rows).
//   L1: per warp  M=32 N=64  K=72 (pad)  -> 2x8x9  m16n8k8 MMAs
//   L2: per warp  M=32 N=128 K=64        -> 2x16x8 m16n8k8 MMAs
//
// smem (32-bit words), all data stored as tf32 bit patterns:
//   aT  [72][264]  A tile k-major  (row = block row 0..255)
//                  -- per-warp aliased by h1T [64][264] after L1 (warp-local
//                     rows only => no block-level barrier between layers)
//   w1s [72][72]   W1^T k-major (zeros for k>=67)
//   w2s [64][136]  W2^T k-major
//   b1s [64] f32, b2s [128] f32
// Fragment-load bank pattern for all three strided arrays:
//   bank = (8*(lane%4) + lane/4) mod 32  -> 32 distinct, conflict-free.
// ---------------------------------------------------------------------------
#define AT_STRIDE 264
#define W1_STRIDE 72
#define W2_STRIDE 136
#define AT_OFF 0
#define W1_OFF (72 * AT_STRIDE)                 // 19008
#define W2_OFF (W1_OFF + 72 * W1_STRIDE)        // 24192
#define B1_OFF (W2_OFF + 64 * W2_STRIDE)        // 32896
#define B2_OFF (B1_OFF + 64)                    // 32960
#define SMEM_WORDS (B2_OFF + 128)               // 33088 (129.25 KB)

__global__ __launch_bounds__(256, 1) void mlp_kernel(
    const float* __restrict__ xyz,
    const int*   __restrict__ idx,
    const float* __restrict__ W1,
    const float* __restrict__ b1,
    const float* __restrict__ W2,
    const float* __restrict__ b2,
    float* __restrict__ out)
{
    extern __shared__ unsigned sm[];
    unsigned* aT  = sm + AT_OFF;
    unsigned* w1s = sm + W1_OFF;
    unsigned* w2s = sm + W2_OFF;
    float* b1s = (float*)(sm + B1_OFF);
    float* b2s = (float*)(sm + B2_OFF);

    const int tid  = threadIdx.x;
    const int lane = tid & 31;
    const int q    = tid >> 5;           // warp == query in block
    const int kk   = lane & 3;
    const int r    = lane >> 2;

    // ---- stage weights (tf32) ----
    for (int i = tid; i < 72 * 64; i += 256) {
        int k = i >> 6, o = i & 63;
        float w = (k < CIN) ? __ldg(&W1[o * CIN + k]) : 0.0f;
        w1s[k * W1_STRIDE + o] = f2tf32(w);
    }
    for (int i = tid; i < 64 * 128; i += 256) {
        int k = i >> 7, o = i & 127;
        w2s[k * W2_STRIDE + o] = f2tf32(__ldg(&W2[o * H1n + k]));
    }
    if (tid < 64)  b1s[tid] = b1[tid];
    if (tid < 128) b2s[tid] = b2[tid];

    // ---- stage A tile (tf32): one block-row per thread ----
    {
        const int gq = blockIdx.x * 8 + q;
        const int b  = gq >> 11;             // NP = 2048
        const int s  = gq & (NP - 1);
        const int n  = lane;
        const int id = idx[(size_t)gq * NS + n];
        const float* xb = xyz + (size_t)b * Nn * 3;

        aT[0 * AT_STRIDE + tid] = f2tf32(__ldg(&xb[id * 3 + 0]) - __ldg(&xb[s * 3 + 0]));
        aT[1 * AT_STRIDE + tid] = f2tf32(__ldg(&xb[id * 3 + 1]) - __ldg(&xb[s * 3 + 1]));
        aT[2 * AT_STRIDE + tid] = f2tf32(__ldg(&xb[id * 3 + 2]) - __ldg(&xb[s * 3 + 2]));
        const float4* fp = (const float4*)(g_featT + ((size_t)b * Nn + id) * Cn);
        #pragma unroll
        for (int k4 = 0; k4 < 16; k4++) {
            float4 v = __ldg(&fp[k4]);
            aT[(3 + 4 * k4 + 0) * AT_STRIDE + tid] = f2tf32(v.x);
            aT[(3 + 4 * k4 + 1) * AT_STRIDE + tid] = f2tf32(v.y);
            aT[(3 + 4 * k4 + 2) * AT_STRIDE + tid] = f2tf32(v.z);
            aT[(3 + 4 * k4 + 3) * AT_STRIDE + tid] = f2tf32(v.w);
        }
        #pragma unroll
        for (int k = 67; k < 72; k++) aT[k * AT_STRIDE + tid] = 0u;
    }
    __syncthreads();

    const int rowbase = q * 32;

    // ---- Layer 1: c1 = W1 . a + b1 (tf32 MMA, fp32 accum) ----
    float c1[2][8][4];
    #pragma unroll
    for (int nt = 0; nt < 8; nt++) {
        float blo = b1s[nt * 8 + 2 * kk];
        float bhi = b1s[nt * 8 + 2 * kk + 1];
        #pragma unroll
        for (int mt = 0; mt < 2; mt++) {
            c1[mt][nt][0] = blo; c1[mt][nt][1] = bhi;
            c1[mt][nt][2] = blo; c1[mt][nt][3] = bhi;
        }
    }

    #pragma unroll
    for (int kg = 0; kg < 9; kg++) {
        const int k0 = kg * 8 + kk;
        unsigned a[2][4];
        #pragma unroll
        for (int mt = 0; mt < 2; mt++) {
            int rb = rowbase + mt * 16 + r;
            a[mt][0] = aT[k0 * AT_STRIDE + rb];
            a[mt][1] = aT[k0 * AT_STRIDE + rb + 8];
            a[mt][2] = aT[(k0 + 4) * AT_STRIDE + rb];
            a[mt][3] = aT[(k0 + 4) * AT_STRIDE + rb + 8];
        }
        #pragma unroll
        for (int nt = 0; nt < 8; nt++) {
            unsigned b[2];
            b[0] = w1s[k0 * W1_STRIDE + nt * 8 + r];
            b[1] = w1s[(k0 + 4) * W1_STRIDE + nt * 8 + r];
            mma_tf32(c1[0][nt], a[0], b);
            mma_tf32(c1[1][nt], a[1], b);
        }
    }
    __syncwarp();

    // ---- store relu(h1) as tf32 into warp-local rows of aT (alias) ----
    #pragma unroll
    for (int mt = 0; mt < 2; mt++)
        #pragma unroll
        for (int nt = 0; nt < 8; nt++)
            #pragma unroll
            for (int i = 0; i < 2; i++)
                #pragma unroll
                for (int j = 0; j < 2; j++) {
                    int col = nt * 8 + 2 * kk + j;
                    int row = rowbase + mt * 16 + r + 8 * i;
                    aT[col * AT_STRIDE + row] = f2tf32(fmaxf(c1[mt][nt][2 * i + j], 0.0f));
                }
    __syncwarp();

    // ---- Layer 2: c2 = W2 . h1 + b2 ----
    float c2[2][16][4];
    #pragma unroll
    for (int nt = 0; nt < 16; nt++) {
        float blo = b2s[nt * 8 + 2 * kk];
        float bhi = b2s[nt * 8 + 2 * kk + 1];
        #pragma unroll
        for (int mt = 0; mt < 2; mt++) {
            c2[mt][nt][0] = blo; c2[mt][nt][1] = bhi;
            c2[mt][nt][2] = blo; c2[mt][nt][3] = bhi;
        }
    }

    #pragma unroll
    for (int kg = 0; kg < 8; kg++) {
        const int k0 = kg * 8 + kk;
        unsigned a[2][4];
        #pragma unroll
        for (int mt = 0; mt < 2; mt++) {
            int rb = rowbase + mt * 16 + r;
            a[mt][0] = aT[k0 * AT_STRIDE + rb];
            a[mt][1] = aT[k0 * AT_STRIDE + rb + 8];
            a[mt][2] = aT[(k0 + 4) * AT_STRIDE + rb];
            a[mt][3] = aT[(k0 + 4) * AT_STRIDE + rb + 8];
        }
        #pragma unroll
        for (int nt = 0; nt < 16; nt++) {
            unsigned b[2];
            b[0] = w2s[k0 * W2_STRIDE + nt * 8 + r];
            b[1] = w2s[(k0 + 4) * W2_STRIDE + nt * 8 + r];
            mma_tf32(c2[0][nt], a[0], b);
            mma_tf32(c2[1][nt], a[1], b);
        }
    }

    // ---- max over 32 rows + relu + write ----
    {
        const int gq = blockIdx.x * 8 + q;
        const int b  = gq >> 11;
        const int s  = gq & (NP - 1);
        float* op_base = out + (Bn * NP * 3) + (size_t)b * H2n * NP + s;

        #pragma unroll
        for (int nt = 0; nt < 16; nt++)
            #pragma unroll
            for (int j = 0; j < 2; j++) {
                float v = fmaxf(fmaxf(c2[0][nt][j], c2[0][nt][j + 2]),
                                fmaxf(c2[1][nt][j], c2[1][nt][j + 2]));
                v = fmaxf(v, __shfl_xor_sync(0xffffffffu, v, 4));
                v = fmaxf(v, __shfl_xor_sync(0xffffffffu, v, 8));
                v = fmaxf(v, __shfl_xor_sync(0xffffffffu, v, 16));
                if (r == 0) {
                    int col = nt * 8 + 2 * kk + j;
                    op_base[(size_t)col * NP] = fmaxf(v, 0.0f);
                }
            }
    }
}

// ---------------------------------------------------------------------------
extern "C" void kernel_launch(void* const* d_in, const int* in_sizes, int n_in,
                              void* d_out, int out_size)
{
    const float* xyz      = (const float*)d_in[0];
    const float* features = (const float*)d_in[1];
    const float* W1       = (const float*)d_in[2];
    const float* b1       = (const float*)d_in[3];
    const float* W2       = (const float*)d_in[4];
    const float* b2       = (const float*)d_in[5];
    float* out = (float*)d_out;

    static bool attr_set = false;
    if (!attr_set) {
        cudaFuncSetAttribute(mlp_kernel, cudaFuncAttributeMaxDynamicSharedMemorySize,
                             SMEM_WORDS * (int)sizeof(unsigned));
        attr_set = true;
    }

    int*   idxp;
    float* ftp;
    cudaGetSymbolAddress((void**)&idxp, g_idx);
    cudaGetSymbolAddress((void**)&ftp, g_featT);

    // 1) transpose features (B,C,N)->(B,N,C)
    {
        dim3 blk(32, 32, 1);
        dim3 grd(Nn / 32, Cn / 32, Bn);
        transpose_kernel<<<grd, blk>>>(features, ftp);
    }
    // 2) ball query + new_xyz copy
    {
        int warps = Bn * NP;
        int threads = 256;
        int blocks = (warps * 32 + threads - 1) / threads;
        bq_kernel<<<blocks, threads>>>(xyz, idxp, out);
    }
    // 3) fused group + MLP + max (8 queries / block, tf32 tensor cores)
    {
        int blocks = (Bn * NP) / 8;
        mlp_kernel<<<blocks, 256, SMEM_WORDS * (int)sizeof(unsigned)>>>(
            xyz, idxp, W1, b1, W2, b2, out);
    }
}